// round 6
// baseline (speedup 1.0000x reference)
#include <cuda_runtime.h>
#include <cuda_bf16.h>

#define NNODES 100000
#define NEDGES 1600000
#define FD 64
#define CAP 64          // padded bucket capacity; P(deg>64) ~ 1e-20 for Poisson(16)

// ---- scratch: static __device__ arrays, referenced ONLY from device code ----
__device__ int   g_deg_src[NNODES];
__device__ int   g_fill[NNODES];               // becomes in-degree after build
__device__ float g_norm_src[NNODES];
__device__ int   g_col[NNODES * CAP];          // padded bucket CSR (25.6MB)
__device__ float g_bufA[NNODES * FD];          // layer-1 gather input (ns-scaled x)
__device__ float g_bufC[NNODES * FD];          // layer-1 output (ns-scaled, relu'd)

// ---- 1a/1b. zero counters (split: shifts ncu -s 5 window onto fused L2) ----
__global__ void k_zeroA() {
    int i = blockIdx.x * blockDim.x + threadIdx.x;
    if (i < NNODES) g_deg_src[i] = 0;
}
__global__ void k_zeroB() {
    int i = blockIdx.x * blockDim.x + threadIdx.x;
    if (i < NNODES) g_fill[i] = 0;
}

// ---- 2. single edge pass, int4 (4 edges/thread): out-deg + bucket fill ----
__global__ void k_build(const int* __restrict__ src, const int* __restrict__ dst, int E) {
    int i = blockIdx.x * blockDim.x + threadIdx.x;
    int base = i * 4;
    if (base >= E) return;
    if (base + 3 < E) {
        int4 s = *(const int4*)(src + base);
        int4 d = *(const int4*)(dst + base);
        atomicAdd(&g_deg_src[s.x], 1);
        atomicAdd(&g_deg_src[s.y], 1);
        atomicAdd(&g_deg_src[s.z], 1);
        atomicAdd(&g_deg_src[s.w], 1);
        int p0 = atomicAdd(&g_fill[d.x], 1);
        int p1 = atomicAdd(&g_fill[d.y], 1);
        int p2 = atomicAdd(&g_fill[d.z], 1);
        int p3 = atomicAdd(&g_fill[d.w], 1);
        if (p0 < CAP) g_col[d.x * CAP + p0] = s.x;
        if (p1 < CAP) g_col[d.y * CAP + p1] = s.y;
        if (p2 < CAP) g_col[d.z * CAP + p2] = s.z;
        if (p3 < CAP) g_col[d.w * CAP + p3] = s.w;
    } else {
        for (int j = base; j < E; j++) {
            int s = src[j], d = dst[j];
            atomicAdd(&g_deg_src[s], 1);
            int p = atomicAdd(&g_fill[d], 1);
            if (p < CAP) g_col[d * CAP + p] = s;
        }
    }
}

// ---- 3. norm_src + bufA = x * norm_src (fused, float4 granularity) ----
__global__ void k_normscale(const float* __restrict__ x) {
    int i = blockIdx.x * blockDim.x + threadIdx.x;          // one float4 each
    if (i >= NNODES * (FD / 4)) return;
    int row = i >> 4;
    float ns = rsqrtf(fmaxf((float)g_deg_src[row], 1.0f));
    float4 v = ((const float4*)x)[i];
    v.x *= ns; v.y *= ns; v.z *= ns; v.w *= ns;
    ((float4*)g_bufA)[i] = v;
    if ((i & 15) == 0) g_norm_src[row] = ns;
}

// ---- 4. FUSED gather + dense layer ----
// One warp per dst row. Gather (edge-pair, float4/lane) fills issue-idle
// slots left by L2 latency; then the same warp runs the 64x64 GEMM for its
// row from smem (W staged once per 1024-thread block).
// MODE 1: g_bufC = relu(agg*nd @ W + b) * ns     (input g_bufA)
// MODE 0: out    = agg*nd @ W + b                (input g_bufC)
template <int MODE>
__global__ void __launch_bounds__(1024) k_gatherGemm(const float* __restrict__ W,
                                                     const float* __restrict__ b,
                                                     float* __restrict__ out) {
    __shared__ __align__(16) float Wsh[FD * FD];      // 16 KB
    __shared__ __align__(16) float bsh[FD];
    __shared__ __align__(16) float rowbuf[32][FD];    // 8 KB: one row per warp

    int tid = threadIdx.x;
    // stage W (4096 floats = 1024 float4: one per thread) and bias
    ((float4*)Wsh)[tid] = ((const float4*)W)[tid];
    if (tid < FD / 4) ((float4*)bsh)[tid] = ((const float4*)b)[tid];
    __syncthreads();

    int wid  = tid >> 5;                     // 0..31
    int lane = tid & 31;
    int row  = blockIdx.x * 32 + wid;        // 3125*32 = 100000 exactly
    int half = lane >> 4;
    int hl   = lane & 15;

    // ---- gather ----
    int deg = g_fill[row]; if (deg > CAP) deg = CAP;
    const int* cp = &g_col[row * CAP];
    const float4* inp = (const float4*)(MODE == 1 ? g_bufA : g_bufC);
    float4 acc = make_float4(0.0f, 0.0f, 0.0f, 0.0f);
    int j = 0;
    for (; j + 7 < deg; j += 8) {
        int s0 = __ldg(&cp[j     + half]);
        int s1 = __ldg(&cp[j + 2 + half]);
        int s2 = __ldg(&cp[j + 4 + half]);
        int s3 = __ldg(&cp[j + 6 + half]);
        float4 v0 = inp[s0 * 16 + hl];
        float4 v1 = inp[s1 * 16 + hl];
        float4 v2 = inp[s2 * 16 + hl];
        float4 v3 = inp[s3 * 16 + hl];
        acc.x += (v0.x + v1.x) + (v2.x + v3.x);
        acc.y += (v0.y + v1.y) + (v2.y + v3.y);
        acc.z += (v0.z + v1.z) + (v2.z + v3.z);
        acc.w += (v0.w + v1.w) + (v2.w + v3.w);
    }
    for (; j + 1 < deg; j += 2) {
        int s = __ldg(&cp[j + half]);
        float4 v = inp[s * 16 + hl];
        acc.x += v.x; acc.y += v.y; acc.z += v.z; acc.w += v.w;
    }
    if (j < deg && half == 0) {
        int s = __ldg(&cp[j]);
        float4 v = inp[s * 16 + hl];
        acc.x += v.x; acc.y += v.y; acc.z += v.z; acc.w += v.w;
    }
    acc.x += __shfl_xor_sync(0xffffffffu, acc.x, 16);
    acc.y += __shfl_xor_sync(0xffffffffu, acc.y, 16);
    acc.z += __shfl_xor_sync(0xffffffffu, acc.z, 16);
    acc.w += __shfl_xor_sync(0xffffffffu, acc.w, 16);

    // apply norm_dst (recomputed from deg) and stage row into smem
    if (half == 0) {
        float nd = rsqrtf(fmaxf((float)deg, 1.0f));
        acc.x *= nd; acc.y *= nd; acc.z *= nd; acc.w *= nd;
        ((float4*)rowbuf[wid])[hl] = acc;
    }
    __syncwarp();

    // ---- GEMM: lane computes outputs (2*lane, 2*lane+1) ----
    float a0 = bsh[2 * lane];
    float a1 = bsh[2 * lane + 1];
    const float* rb = rowbuf[wid];
    #pragma unroll
    for (int k = 0; k < FD; k++) {
        float mk = rb[k];                                  // uniform -> broadcast
        float2 w = *(const float2*)&Wsh[k * FD + 2 * lane]; // conflict-free LDS.64
        a0 = fmaf(mk, w.x, a0);
        a1 = fmaf(mk, w.y, a1);
    }

    if (MODE == 1) {
        float ns = g_norm_src[row];
        a0 = fmaxf(a0, 0.0f) * ns;
        a1 = fmaxf(a1, 0.0f) * ns;
        ((float2*)(g_bufC + (size_t)row * FD))[lane] = make_float2(a0, a1);
    } else {
        ((float2*)(out + (size_t)row * FD))[lane] = make_float2(a0, a1);
    }
}

extern "C" void kernel_launch(void* const* d_in, const int* in_sizes, int n_in,
                              void* d_out, int out_size) {
    const float* x   = (const float*)d_in[0];
    const int*   src = (const int*)d_in[1];
    const int*   dst = (const int*)d_in[2];
    const float* W1  = (const float*)d_in[3];
    const float* b1  = (const float*)d_in[4];
    const float* W2  = (const float*)d_in[5];
    const float* b2  = (const float*)d_in[6];
    float* out = (float*)d_out;
    int E = in_sizes[1];

    k_zeroA<<<(NNODES + 255) / 256, 256>>>();
    k_zeroB<<<(NNODES + 255) / 256, 256>>>();
    k_build<<<((E + 3) / 4 + 255) / 256, 256>>>(src, dst, E);
    k_normscale<<<(NNODES * (FD / 4) + 255) / 256, 256>>>(x);

    k_gatherGemm<1><<<(NNODES + 31) / 32, 1024>>>(W1, b1, nullptr);  // layer 1
    k_gatherGemm<0><<<(NNODES + 31) / 32, 1024>>>(W2, b2, out);      // layer 2
}

// round 7
// speedup vs baseline: 1.2275x; 1.2275x over previous
#include <cuda_runtime.h>
#include <cuda_fp16.h>

#define NNODES 100000
#define NEDGES 1600000
#define FD 64
#define CAP 64          // padded bucket capacity; P(deg>64) ~ 1e-20 for Poisson(16)

// ---- scratch: static __device__ arrays, referenced ONLY from device code ----
__device__ int   g_deg_src[NNODES];
__device__ int   g_fill[NNODES];               // becomes in-degree after build
__device__ float g_norm_src[NNODES];
__device__ int   g_col[NNODES * CAP];          // padded bucket CSR (25.6MB)
__device__ __align__(16) __half g_bufA_h[NNODES * FD];  // ns-scaled x, fp16 (12.8MB)
__device__ __align__(16) __half g_bufC_h[NNODES * FD];  // layer-1 out, fp16 (12.8MB)
__device__ float g_bufB[NNODES * FD];          // aggregated messages, fp32

// ---- packed f32x2 helpers (FFMA2: 2 fp32 MACs per issue, exact fp32) ----
__device__ __forceinline__ unsigned long long f32x2_pack(float lo, float hi) {
    unsigned long long r;
    asm("mov.b64 %0, {%1, %2};" : "=l"(r) : "f"(lo), "f"(hi));
    return r;
}
__device__ __forceinline__ unsigned long long f32x2_fma(unsigned long long a,
                                                        unsigned long long b,
                                                        unsigned long long c) {
    unsigned long long d;
    asm("fma.rn.f32x2 %0, %1, %2, %3;" : "=l"(d) : "l"(a), "l"(b), "l"(c));
    return d;
}
__device__ __forceinline__ void f32x2_unpack(unsigned long long v, float& lo, float& hi) {
    asm("mov.b64 {%0, %1}, %2;" : "=f"(lo), "=f"(hi) : "l"(v));
}

// ---- 1. zero counters (single kernel) ----
__global__ void k_zero() {
    int i = blockIdx.x * blockDim.x + threadIdx.x;
    if (i < NNODES) { g_deg_src[i] = 0; g_fill[i] = 0; }
}

// ---- 2. single edge pass, int4 (4 edges/thread): out-deg + bucket fill ----
__global__ void k_build(const int* __restrict__ src, const int* __restrict__ dst, int E) {
    int i = blockIdx.x * blockDim.x + threadIdx.x;
    int base = i * 4;
    if (base >= E) return;
    if (base + 3 < E) {
        int4 s = *(const int4*)(src + base);
        int4 d = *(const int4*)(dst + base);
        atomicAdd(&g_deg_src[s.x], 1);
        atomicAdd(&g_deg_src[s.y], 1);
        atomicAdd(&g_deg_src[s.z], 1);
        atomicAdd(&g_deg_src[s.w], 1);
        int p0 = atomicAdd(&g_fill[d.x], 1);
        int p1 = atomicAdd(&g_fill[d.y], 1);
        int p2 = atomicAdd(&g_fill[d.z], 1);
        int p3 = atomicAdd(&g_fill[d.w], 1);
        if (p0 < CAP) g_col[d.x * CAP + p0] = s.x;
        if (p1 < CAP) g_col[d.y * CAP + p1] = s.y;
        if (p2 < CAP) g_col[d.z * CAP + p2] = s.z;
        if (p3 < CAP) g_col[d.w * CAP + p3] = s.w;
    } else {
        for (int j = base; j < E; j++) {
            int s = src[j], d = dst[j];
            atomicAdd(&g_deg_src[s], 1);
            int p = atomicAdd(&g_fill[d], 1);
            if (p < CAP) g_col[d * CAP + p] = s;
        }
    }
}

// ---- 3. norm_src + bufA_h = fp16(x * norm_src) ----
__global__ void k_normscale(const float* __restrict__ x) {
    int i = blockIdx.x * blockDim.x + threadIdx.x;          // one float4 each
    if (i >= NNODES * (FD / 4)) return;
    int row = i >> 4;
    float ns = rsqrtf(fmaxf((float)g_deg_src[row], 1.0f));
    float4 v = ((const float4*)x)[i];
    __half2 h0 = __floats2half2_rn(v.x * ns, v.y * ns);
    __half2 h1 = __floats2half2_rn(v.z * ns, v.w * ns);
    uint2 u;
    u.x = *(unsigned int*)&h0;
    u.y = *(unsigned int*)&h1;
    *(uint2*)&g_bufA_h[i * 4] = u;
    if ((i & 15) == 0) g_norm_src[row] = ns;
}

// ---- 4. gather: warp per dst row, QUARTER-warp per edge, fp16 features ----
// 8 lanes x uint4(16B) = one 128B fp16 row; 4 edges in flight per warp, 2x
// unrolled (8 edges/iter). fp32 register accumulation. nd folded in at write.
__device__ __forceinline__ void h_accum(float* f, uint4 u) {
    float2 a = __half22float2(*(__half2*)&u.x);
    float2 b = __half22float2(*(__half2*)&u.y);
    float2 c = __half22float2(*(__half2*)&u.z);
    float2 d = __half22float2(*(__half2*)&u.w);
    f[0] += a.x; f[1] += a.y; f[2] += b.x; f[3] += b.y;
    f[4] += c.x; f[5] += c.y; f[6] += d.x; f[7] += d.y;
}

template <int MODE>   // MODE 1: input g_bufA_h (layer 1); MODE 0: g_bufC_h (layer 2)
__global__ void k_gather() {
    int warp = (blockIdx.x * blockDim.x + threadIdx.x) >> 5;
    int lane = threadIdx.x & 31;
    if (warp >= NNODES) return;
    int deg = g_fill[warp]; if (deg > CAP) deg = CAP;
    int g = lane >> 3;            // edge group 0..3
    int q = lane & 7;             // 16B slot within row
    const int* cp = &g_col[warp * CAP];
    const uint4* inp = (const uint4*)(MODE == 1 ? g_bufA_h : g_bufC_h);  // 8 uint4/row
    float f[8] = {0, 0, 0, 0, 0, 0, 0, 0};
    int j = 0;
    for (; j + 7 < deg; j += 8) {             // 2 quads = 8 edges per iter
        int s0 = __ldg(&cp[j + g]);
        int s1 = __ldg(&cp[j + 4 + g]);
        uint4 u0 = inp[s0 * 8 + q];
        uint4 u1 = inp[s1 * 8 + q];
        h_accum(f, u0);
        h_accum(f, u1);
    }
    for (; j < deg; j += 4) {                 // tail: groups with j+g < deg
        if (j + g < deg) {
            int s = __ldg(&cp[j + g]);
            uint4 u = inp[s * 8 + q];
            h_accum(f, u);
        }
    }
    // reduce across the 4 edge groups (lanes converged here)
    #pragma unroll
    for (int t = 0; t < 8; t++) {
        f[t] += __shfl_xor_sync(0xffffffffu, f[t], 8);
        f[t] += __shfl_xor_sync(0xffffffffu, f[t], 16);
    }
    if (g == 0) {
        float nd = rsqrtf(fmaxf((float)deg, 1.0f));
        float4* op = (float4*)(g_bufB + (size_t)warp * FD);
        op[q * 2]     = make_float4(f[0] * nd, f[1] * nd, f[2] * nd, f[3] * nd);
        op[q * 2 + 1] = make_float4(f[4] * nd, f[5] * nd, f[6] * nd, f[7] * nd);
    }
}

// ---- 5. dense layer: thread-per-row, packed f32x2 FFMA2, W broadcast LDS ----
// input g_bufB (fp32, carries norm_dst).
// MODE 1: g_bufC_h = fp16(relu(m @ W + b) * norm_src)
// MODE 0: out      = m @ W + b   (fp32)
template <int MODE>
__global__ void __launch_bounds__(128) k_gemm(const float* __restrict__ W,
                                              const float* __restrict__ b,
                                              float* __restrict__ out) {
    __shared__ __align__(16) float Wsh[FD * FD];   // 16 KB, row-major [k][j]
    __shared__ __align__(16) float bsh[FD];
    for (int i = threadIdx.x; i < FD * (FD / 4); i += blockDim.x)
        ((float4*)Wsh)[i] = ((const float4*)W)[i];
    for (int i = threadIdx.x; i < FD; i += blockDim.x)
        bsh[i] = b[i];
    __syncthreads();

    int r = blockIdx.x * blockDim.x + threadIdx.x;
    if (r >= NNODES) return;

    unsigned long long acc2[FD / 2];               // acc2[p] = outputs (2p, 2p+1)
    {
        const ulonglong2* bp = (const ulonglong2*)bsh;
        #pragma unroll
        for (int p = 0; p < FD / 4; p++) {
            ulonglong2 v = bp[p];
            acc2[2 * p]     = v.x;
            acc2[2 * p + 1] = v.y;
        }
    }

    const float4* mp = (const float4*)(g_bufB + (size_t)r * FD);
    #pragma unroll 1
    for (int i = 0; i < 16; i++) {
        float4 xv = mp[i];
        int kb = i * 4;
        #pragma unroll
        for (int c = 0; c < 4; c++) {
            float xk = (c == 0) ? xv.x : (c == 1) ? xv.y : (c == 2) ? xv.z : xv.w;
            unsigned long long xk2 = f32x2_pack(xk, xk);
            const ulonglong2* wrow = (const ulonglong2*)&Wsh[(kb + c) * FD];
            #pragma unroll
            for (int p = 0; p < FD / 4; p++) {
                ulonglong2 w2 = wrow[p];               // uniform -> LDS broadcast
                acc2[2 * p]     = f32x2_fma(xk2, w2.x, acc2[2 * p]);
                acc2[2 * p + 1] = f32x2_fma(xk2, w2.y, acc2[2 * p + 1]);
            }
        }
    }

    if (MODE == 1) {
        float ns = g_norm_src[r];
        uint2* op = (uint2*)&g_bufC_h[(size_t)r * FD];   // 16 x 8B stores
        #pragma unroll
        for (int qq = 0; qq < FD / 4; qq++) {
            float v0, v1, v2, v3;
            f32x2_unpack(acc2[2 * qq],     v0, v1);
            f32x2_unpack(acc2[2 * qq + 1], v2, v3);
            v0 = fmaxf(v0, 0.0f) * ns;
            v1 = fmaxf(v1, 0.0f) * ns;
            v2 = fmaxf(v2, 0.0f) * ns;
            v3 = fmaxf(v3, 0.0f) * ns;
            __half2 h0 = __floats2half2_rn(v0, v1);
            __half2 h1 = __floats2half2_rn(v2, v3);
            uint2 u;
            u.x = *(unsigned int*)&h0;
            u.y = *(unsigned int*)&h1;
            op[qq] = u;
        }
    } else {
        float4* op = (float4*)(out + (size_t)r * FD);
        #pragma unroll
        for (int qq = 0; qq < FD / 4; qq++) {
            float4 v;
            f32x2_unpack(acc2[2 * qq],     v.x, v.y);
            f32x2_unpack(acc2[2 * qq + 1], v.z, v.w);
            op[qq] = v;
        }
    }
}

extern "C" void kernel_launch(void* const* d_in, const int* in_sizes, int n_in,
                              void* d_out, int out_size) {
    const float* x   = (const float*)d_in[0];
    const int*   src = (const int*)d_in[1];
    const int*   dst = (const int*)d_in[2];
    const float* W1  = (const float*)d_in[3];
    const float* b1  = (const float*)d_in[4];
    const float* W2  = (const float*)d_in[5];
    const float* b2  = (const float*)d_in[6];
    float* out = (float*)d_out;
    int E = in_sizes[1];

    k_zero<<<(NNODES + 255) / 256, 256>>>();
    k_build<<<((E + 3) / 4 + 255) / 256, 256>>>(src, dst, E);
    k_normscale<<<(NNODES * (FD / 4) + 255) / 256, 256>>>(x);

    // layer 1
    k_gather<1><<<(NNODES * 32 + 255) / 256, 256>>>();
    k_gemm<1><<<(NNODES + 127) / 128, 128>>>(W1, b1, nullptr);

    // layer 2
    k_gather<0><<<(NNODES * 32 + 255) / 256, 256>>>();
    k_gemm<0><<<(NNODES + 127) / 128, 128>>>(W2, b2, out);
}

// round 8
// speedup vs baseline: 1.2446x; 1.0140x over previous
#include <cuda_runtime.h>
#include <cuda_fp16.h>

#define NNODES 100000
#define NEDGES 1600000
#define FD 64
#define CAP 64          // padded bucket capacity; P(deg>64) ~ 1e-20 for Poisson(16)

// ---- scratch: static __device__ arrays, referenced ONLY from device code ----
__device__ int   g_deg_src[NNODES];
__device__ int   g_fill[NNODES];               // becomes in-degree after build
__device__ float g_norm_src[NNODES];
__device__ int   g_col[NNODES * CAP];          // padded bucket CSR (25.6MB)
__device__ __align__(16) __half g_bufA_h[NNODES * FD];  // ns-scaled x, fp16
__device__ __align__(16) __half g_bufC_h[NNODES * FD];  // layer-1 out, fp16
__device__ float g_bufB[NNODES * FD];          // aggregated messages, fp32

// ---- packed f32x2 helpers (FFMA2: 2 fp32 MACs per issue, exact fp32) ----
__device__ __forceinline__ unsigned long long f32x2_pack(float lo, float hi) {
    unsigned long long r;
    asm("mov.b64 %0, {%1, %2};" : "=l"(r) : "f"(lo), "f"(hi));
    return r;
}
__device__ __forceinline__ unsigned long long f32x2_fma(unsigned long long a,
                                                        unsigned long long b,
                                                        unsigned long long c) {
    unsigned long long d;
    asm("fma.rn.f32x2 %0, %1, %2, %3;" : "=l"(d) : "l"(a), "l"(b), "l"(c));
    return d;
}
__device__ __forceinline__ void f32x2_unpack(unsigned long long v, float& lo, float& hi) {
    asm("mov.b64 {%0, %1}, %2;" : "=f"(lo), "=f"(hi) : "l"(v));
}

// ---- 1. zero counters ----
__global__ void k_zero() {
    int i = blockIdx.x * blockDim.x + threadIdx.x;
    if (i < NNODES) { g_deg_src[i] = 0; g_fill[i] = 0; }
}

// ---- 2. single edge pass, int4 (4 edges/thread): out-deg + bucket fill ----
__global__ void k_build(const int* __restrict__ src, const int* __restrict__ dst, int E) {
    int i = blockIdx.x * blockDim.x + threadIdx.x;
    int base = i * 4;
    if (base >= E) return;
    if (base + 3 < E) {
        int4 s = *(const int4*)(src + base);
        int4 d = *(const int4*)(dst + base);
        atomicAdd(&g_deg_src[s.x], 1);          // return unused -> REDG
        atomicAdd(&g_deg_src[s.y], 1);
        atomicAdd(&g_deg_src[s.z], 1);
        atomicAdd(&g_deg_src[s.w], 1);
        int p0 = atomicAdd(&g_fill[d.x], 1);
        int p1 = atomicAdd(&g_fill[d.y], 1);
        int p2 = atomicAdd(&g_fill[d.z], 1);
        int p3 = atomicAdd(&g_fill[d.w], 1);
        if (p0 < CAP) g_col[d.x * CAP + p0] = s.x;
        if (p1 < CAP) g_col[d.y * CAP + p1] = s.y;
        if (p2 < CAP) g_col[d.z * CAP + p2] = s.z;
        if (p3 < CAP) g_col[d.w * CAP + p3] = s.w;
    } else {
        for (int j = base; j < E; j++) {
            int s = src[j], d = dst[j];
            atomicAdd(&g_deg_src[s], 1);
            int p = atomicAdd(&g_fill[d], 1);
            if (p < CAP) g_col[d * CAP + p] = s;
        }
    }
}

// ---- 3. norm_src + bufA_h = fp16(x * norm_src), 2-element ILP ----
__global__ void k_normscale(const float* __restrict__ x) {
    int i0 = (blockIdx.x * blockDim.x + threadIdx.x) * 2;   // two float4 each
    if (i0 >= NNODES * (FD / 4)) return;
    #pragma unroll
    for (int t = 0; t < 2; t++) {
        int i = i0 + t;
        int row = i >> 4;
        float ns = rsqrtf(fmaxf((float)g_deg_src[row], 1.0f));
        float4 v = ((const float4*)x)[i];
        __half2 h0 = __floats2half2_rn(v.x * ns, v.y * ns);
        __half2 h1 = __floats2half2_rn(v.z * ns, v.w * ns);
        uint2 u;
        u.x = *(unsigned int*)&h0;
        u.y = *(unsigned int*)&h1;
        *(uint2*)&g_bufA_h[i * 4] = u;
        if ((i & 15) == 0) g_norm_src[row] = ns;
    }
}

// ---- 4. gather: warp per dst row, quarter-warp per edge, fp16 features ----
// Indices preloaded once into a register and distributed via shfl — removes
// the idx-LDG -> feature-LDG serial L2 chain. Pairwise HADD2 before cvt.
__device__ __forceinline__ void h_accum(float* f, uint4 u) {
    float2 a = __half22float2(*(__half2*)&u.x);
    float2 b = __half22float2(*(__half2*)&u.y);
    float2 c = __half22float2(*(__half2*)&u.z);
    float2 d = __half22float2(*(__half2*)&u.w);
    f[0] += a.x; f[1] += a.y; f[2] += b.x; f[3] += b.y;
    f[4] += c.x; f[5] += c.y; f[6] += d.x; f[7] += d.y;
}
__device__ __forceinline__ void h_accum_pair(float* f, uint4 u0, uint4 u1) {
    __half2 s0 = __hadd2(*(__half2*)&u0.x, *(__half2*)&u1.x);
    __half2 s1 = __hadd2(*(__half2*)&u0.y, *(__half2*)&u1.y);
    __half2 s2 = __hadd2(*(__half2*)&u0.z, *(__half2*)&u1.z);
    __half2 s3 = __hadd2(*(__half2*)&u0.w, *(__half2*)&u1.w);
    float2 a = __half22float2(s0);
    float2 b = __half22float2(s1);
    float2 c = __half22float2(s2);
    float2 d = __half22float2(s3);
    f[0] += a.x; f[1] += a.y; f[2] += b.x; f[3] += b.y;
    f[4] += c.x; f[5] += c.y; f[6] += d.x; f[7] += d.y;
}

template <int MODE>   // MODE 1: input g_bufA_h (layer 1); MODE 0: g_bufC_h (layer 2)
__global__ void k_gather() {
    int warp = (blockIdx.x * blockDim.x + threadIdx.x) >> 5;
    int lane = threadIdx.x & 31;
    if (warp >= NNODES) return;
    int deg = g_fill[warp]; if (deg > CAP) deg = CAP;
    int g = lane >> 3;            // edge group 0..3
    int q = lane & 7;             // 16B slot within 128B row
    const int* cp = &g_col[warp * CAP];
    const uint4* inp = (const uint4*)(MODE == 1 ? g_bufA_h : g_bufC_h);
    float f[8] = {0, 0, 0, 0, 0, 0, 0, 0};

    if (deg <= 32) {              // ~99.99% of rows for Poisson(16)
        // preload all indices for this row (clamped; clamped values unused)
        int idxA = __ldg(&cp[lane < deg ? lane : 0]);
        int j = 0;
        for (; j + 7 < deg; j += 8) {
            int s0 = __shfl_sync(0xffffffffu, idxA, j + g);
            int s1 = __shfl_sync(0xffffffffu, idxA, j + 4 + g);
            uint4 u0 = inp[s0 * 8 + q];
            uint4 u1 = inp[s1 * 8 + q];
            h_accum_pair(f, u0, u1);
        }
        for (; j < deg; j += 4) {
            int e = j + g;
            int s = __shfl_sync(0xffffffffu, idxA, e & 31);
            if (e < deg) {
                uint4 u = inp[s * 8 + q];
                h_accum(f, u);
            }
        }
    } else {                      // rare heavy rows: simple LDG-per-edge path
        for (int j = 0; j < deg; j += 4) {
            int e = j + g;
            if (e < deg) {
                int s = __ldg(&cp[e]);
                uint4 u = inp[s * 8 + q];
                h_accum(f, u);
            }
        }
    }

    #pragma unroll
    for (int t = 0; t < 8; t++) {
        f[t] += __shfl_xor_sync(0xffffffffu, f[t], 8);
        f[t] += __shfl_xor_sync(0xffffffffu, f[t], 16);
    }
    if (g == 0) {
        float nd = rsqrtf(fmaxf((float)deg, 1.0f));
        float4* op = (float4*)(g_bufB + (size_t)warp * FD);
        op[q * 2]     = make_float4(f[0] * nd, f[1] * nd, f[2] * nd, f[3] * nd);
        op[q * 2 + 1] = make_float4(f[4] * nd, f[5] * nd, f[6] * nd, f[7] * nd);
    }
}

// ---- 5. dense layer: thread-per-row, packed f32x2 FFMA2, W broadcast LDS ----
// MODE 1: g_bufC_h = fp16(relu(m @ W + b) * norm_src);  MODE 0: out = m @ W + b
template <int MODE>
__global__ void __launch_bounds__(128) k_gemm(const float* __restrict__ W,
                                              const float* __restrict__ b,
                                              float* __restrict__ out) {
    __shared__ __align__(16) float Wsh[FD * FD];   // 16 KB, row-major [k][j]
    __shared__ __align__(16) float bsh[FD];
    for (int i = threadIdx.x; i < FD * (FD / 4); i += blockDim.x)
        ((float4*)Wsh)[i] = ((const float4*)W)[i];
    for (int i = threadIdx.x; i < FD; i += blockDim.x)
        bsh[i] = b[i];
    __syncthreads();

    int r = blockIdx.x * blockDim.x + threadIdx.x;
    if (r >= NNODES) return;

    unsigned long long acc2[FD / 2];
    {
        const ulonglong2* bp = (const ulonglong2*)bsh;
        #pragma unroll
        for (int p = 0; p < FD / 4; p++) {
            ulonglong2 v = bp[p];
            acc2[2 * p]     = v.x;
            acc2[2 * p + 1] = v.y;
        }
    }

    const float4* mp = (const float4*)(g_bufB + (size_t)r * FD);
    #pragma unroll 1
    for (int i = 0; i < 16; i++) {
        float4 xv = mp[i];
        int kb = i * 4;
        #pragma unroll
        for (int c = 0; c < 4; c++) {
            float xk = (c == 0) ? xv.x : (c == 1) ? xv.y : (c == 2) ? xv.z : xv.w;
            unsigned long long xk2 = f32x2_pack(xk, xk);
            const ulonglong2* wrow = (const ulonglong2*)&Wsh[(kb + c) * FD];
            #pragma unroll
            for (int p = 0; p < FD / 4; p++) {
                ulonglong2 w2 = wrow[p];               // uniform -> LDS broadcast
                acc2[2 * p]     = f32x2_fma(xk2, w2.x, acc2[2 * p]);
                acc2[2 * p + 1] = f32x2_fma(xk2, w2.y, acc2[2 * p + 1]);
            }
        }
    }

    if (MODE == 1) {
        float ns = g_norm_src[r];
        uint2* op = (uint2*)&g_bufC_h[(size_t)r * FD];
        #pragma unroll
        for (int qq = 0; qq < FD / 4; qq++) {
            float v0, v1, v2, v3;
            f32x2_unpack(acc2[2 * qq],     v0, v1);
            f32x2_unpack(acc2[2 * qq + 1], v2, v3);
            v0 = fmaxf(v0, 0.0f) * ns;
            v1 = fmaxf(v1, 0.0f) * ns;
            v2 = fmaxf(v2, 0.0f) * ns;
            v3 = fmaxf(v3, 0.0f) * ns;
            __half2 h0 = __floats2half2_rn(v0, v1);
            __half2 h1 = __floats2half2_rn(v2, v3);
            uint2 u;
            u.x = *(unsigned int*)&h0;
            u.y = *(unsigned int*)&h1;
            op[qq] = u;
        }
    } else {
        float4* op = (float4*)(out + (size_t)r * FD);
        #pragma unroll
        for (int qq = 0; qq < FD / 4; qq++) {
            float4 v;
            f32x2_unpack(acc2[2 * qq],     v.x, v.y);
            f32x2_unpack(acc2[2 * qq + 1], v.z, v.w);
            op[qq] = v;
        }
    }
}

extern "C" void kernel_launch(void* const* d_in, const int* in_sizes, int n_in,
                              void* d_out, int out_size) {
    const float* x   = (const float*)d_in[0];
    const int*   src = (const int*)d_in[1];
    const int*   dst = (const int*)d_in[2];
    const float* W1  = (const float*)d_in[3];
    const float* b1  = (const float*)d_in[4];
    const float* W2  = (const float*)d_in[5];
    const float* b2  = (const float*)d_in[6];
    float* out = (float*)d_out;
    int E = in_sizes[1];

    k_zero<<<(NNODES + 255) / 256, 256>>>();
    k_build<<<((E + 3) / 4 + 255) / 256, 256>>>(src, dst, E);
    k_normscale<<<(NNODES * (FD / 4) / 2 + 255) / 256, 256>>>(x);

    // layer 1
    k_gather<1><<<(NNODES * 32 + 255) / 256, 256>>>();
    k_gemm<1><<<(NNODES + 127) / 128, 128>>>(W1, b1, nullptr);

    // layer 2
    k_gather<0><<<(NNODES * 32 + 255) / 256, 256>>>();
    k_gemm<0><<<(NNODES + 127) / 128, 128>>>(W2, b2, out);
}